// round 8
// baseline (speedup 1.0000x reference)
#include <cuda_runtime.h>
#include <cuda_fp16.h>
#include <cstdint>

#define EMB      128
#define NRAD     16
#define N_ATOMS_ 100000
#define N_EDGES_ 1000000
#define N_ELEM   95
#define TILE     128
#define NTILES   ((N_EDGES_ + TILE - 1) / TILE)   // 7813
#define GRID_MAIN 296
#define THREADS  256

// ---------------- smem layout (bytes) ----------------
#define OFF_BT2   0                    // W3^T fp16 frags [ks(8)][n(128)][16h] = 32KB
#define OFF_BT1   32768                // W_rbf^T fp16 frags [n(128)][16h]     = 4KB
#define OFF_RBFH  36864                // rbf tile fp16 A-frag, x2 buffers     = 8KB
#define OFF_BIAS  45056                // b_rbf [128] f32
#define OFF_ZI    45568                // zi x2 buffers
#define OFF_ZJ    46592                // zj x2 buffers
#define SMEM_TOTAL 47616

__device__ float g_EW1[N_ELEM * EMB];
__device__ float g_EW2[N_ELEM * EMB];

// ---------------- helpers ----------------
__device__ __forceinline__ float silu_tanh(float x) {
    float t;
    asm("tanh.approx.f32 %0, %1;" : "=f"(t) : "f"(0.5f * x));
    return 0.5f * x * (1.0f + t);
}
__device__ __forceinline__ uint32_t pack2(float lo, float hi) {
    uint32_t r;
    asm("cvt.rn.f16x2.f32 %0, %1, %2;" : "=r"(r) : "f"(hi), "f"(lo));
    return r;
}
__device__ __forceinline__ void mma_f16(float* d,
    uint32_t a0, uint32_t a1, uint32_t a2, uint32_t a3,
    uint32_t b0, uint32_t b1) {
    asm volatile(
        "mma.sync.aligned.m16n8k16.row.col.f32.f16.f16.f32 "
        "{%0,%1,%2,%3}, {%4,%5,%6,%7}, {%8,%9}, {%0,%1,%2,%3};"
        : "+f"(d[0]), "+f"(d[1]), "+f"(d[2]), "+f"(d[3])
        : "r"(a0), "r"(a1), "r"(a2), "r"(a3), "r"(b0), "r"(b1));
}
// physical half position inside a 16-half (32B) chunk so thread c's uint2 at
// byte 8c holds halfs {2c, 2c+1, 2c+8, 2c+9} (== mma fragment pairs)
__device__ __forceinline__ int physmap(int kk) {
    return 4 * ((kk & 7) >> 1) + 2 * (kk >> 3) + (kk & 1);
}

// ---------------- precompute: EW1 = emb@W1 + b, EW2 = emb@W2 ----------------
__global__ void prep_kernel(const float* __restrict__ emb, const float* __restrict__ W,
                            const float* __restrict__ b) {
    __shared__ float p1[EMB], p2[EMB];
    int z = blockIdx.x, n = threadIdx.x & 127, h = threadIdx.x >> 7;
    const float* er = emb + z * EMB;
    float s1 = 0.0f, s2 = 0.0f;
    int k0 = h * 64;
#pragma unroll 8
    for (int k = k0; k < k0 + 64; k++) {
        float ev = er[k];
        s1 += ev * W[k * EMB + n];
        s2 += ev * W[(EMB + k) * EMB + n];
    }
    if (h) { p1[n] = s1; p2[n] = s2; }
    __syncthreads();
    if (!h) {
        g_EW1[z * EMB + n] = s1 + p1[n] + b[n];
        g_EW2[z * EMB + n] = s2 + p2[n];
    }
}

// ---------------- main fused edge kernel (also does x_0 copy) ----------------
__global__ void __launch_bounds__(THREADS, 2)
main_kernel(const int* __restrict__ Z, const float* __restrict__ rbf,
            const int* __restrict__ idx_i, const int* __restrict__ idx_j,
            const float* __restrict__ W_rbf, const float* __restrict__ b_rbf,
            const float* __restrict__ W, float* __restrict__ out,
            const float* __restrict__ emb, float* __restrict__ out0) {
    __shared__ char smem[SMEM_TOTAL];
    const int tid  = threadIdx.x;
    const int wid  = tid >> 5, lane = tid & 31;
    const int q    = lane >> 2, c = lane & 3;
    const int m0   = (wid & 3) * 32;     // warp's 32 rows (2 m-tiles)
    const int n0   = (wid >> 2) * 64;    // warp's n-half

    // staging maps
    const int prow = tid >> 1, ph = tid & 1;     // rbf: 2 threads/row
    const int zrow = tid & 127, zsel = tid >> 7; // z: 128 zi + 128 zj

    // ---- x_0 = embeddings[Z] (independent; overlaps smem fills) ----
    for (int i = blockIdx.x * THREADS + tid; i < N_ATOMS_ * (EMB / 4);
         i += GRID_MAIN * THREADS) {
        int a = i >> 5, qq = i & 31;
        ((float4*)out0)[(size_t)a * 32 + qq] = ((const float4*)emb)[(size_t)Z[a] * 32 + qq];
    }

    // ---- one-time fills ----
    for (int idx = tid; idx < EMB * NRAD; idx += THREADS) {
        int n = idx & 127, k = idx >> 7;
        __half h = __float2half(W_rbf[k * EMB + n]);
        *(unsigned short*)(smem + OFF_BT1 + n * 32 + physmap(k) * 2) = __half_as_ushort(h);
    }
    for (int idx = tid; idx < EMB * EMB; idx += THREADS) {
        int n = idx & 127, k = idx >> 7;
        __half h = __float2half(W[(2 * EMB + k) * EMB + n]);   // W3[k][n]
        int ks = k >> 4, kk = k & 15;
        *(unsigned short*)(smem + OFF_BT2 + ks * 4096 + n * 32 + physmap(kk) * 2) =
            __half_as_ushort(h);
    }
    if (tid < EMB) ((float*)(smem + OFF_BIAS))[tid] = b_rbf[tid];

    // ---- prologue: stage first tile into buffer 0 ----
    int t = blockIdx.x;
    {
        long eb = (long)t * TILE;
        long e  = eb + prow; if (e >= N_EDGES_) e = N_EDGES_ - 1;
        float4 a = ((const float4*)rbf)[e * 4 + 2 * ph];
        float4 b = ((const float4*)rbf)[e * 4 + 2 * ph + 1];
        long ez = eb + zrow; if (ez >= N_EDGES_) ez = N_EDGES_ - 1;
        int pz = Z[(zsel ? idx_j : idx_i)[ez]];
        uint32_t* dst = (uint32_t*)(smem + OFF_RBFH + prow * 32 + ph * 4);
        dst[0] = pack2(a.x, a.y); dst[2] = pack2(a.z, a.w);
        dst[4] = pack2(b.x, b.y); dst[6] = pack2(b.z, b.w);
        ((int*)(smem + (zsel ? OFF_ZJ : OFF_ZI)))[zrow] = pz;
    }
    __syncthreads();

    int buf = 0;
    for (; t < NTILES; t += GRID_MAIN) {
        // ---- prefetch next tile's staging data ----
        float4 pa, pb; int pz;
        {
            int tn = t + GRID_MAIN;
            long eb = (long)(tn < NTILES ? tn : t) * TILE;
            long e  = eb + prow; if (e >= N_EDGES_) e = N_EDGES_ - 1;
            pa = ((const float4*)rbf)[e * 4 + 2 * ph];
            pb = ((const float4*)rbf)[e * 4 + 2 * ph + 1];
            long ez = eb + zrow; if (ez >= N_EDGES_) ez = N_EDGES_ - 1;
            pz = Z[(zsel ? idx_j : idx_i)[ez]];
        }

        const long base = (long)t * TILE;
        const char* rb  = smem + OFF_RBFH + buf * 4096;
        const int* zi_s = (const int*)(smem + OFF_ZI + buf * 512);
        const int* zj_s = (const int*)(smem + OFF_ZJ + buf * 512);

        // ---- A operands for GEMM1 (this warp's 32 rows = 2 m-tiles) ----
        uint2 arlo[2], arhi[2];
#pragma unroll
        for (int mt = 0; mt < 2; mt++) {
            int r = m0 + 16 * mt + q;
            arlo[mt] = *(const uint2*)(rb + r * 32 + 8 * c);
            arhi[mt] = *(const uint2*)(rb + (r + 8) * 32 + 8 * c);
        }

        // ---- fused GEMM1 -> silu -> GEMM2, one k-step at a time ----
        float dacc[2][8][4];
#pragma unroll
        for (int mt = 0; mt < 2; mt++)
#pragma unroll
            for (int nt = 0; nt < 8; nt++)
#pragma unroll
                for (int r = 0; r < 4; r++) dacc[mt][nt][r] = 0.0f;

        const float* bias_s = (const float*)(smem + OFF_BIAS);
#pragma unroll
        for (int ks = 0; ks < 8; ks++) {
            uint32_t afrag[2][4];
#pragma unroll
            for (int half = 0; half < 2; half++) {
                int nt1 = 2 * ks + half;
                uint2 bv = *(const uint2*)(smem + OFF_BT1 + (8 * nt1 + q) * 32 + 8 * c);
                float2 bb = *(const float2*)(bias_s + 8 * nt1 + 2 * c);
#pragma unroll
                for (int mt = 0; mt < 2; mt++) {
                    float d[4] = {bb.x, bb.y, bb.x, bb.y};
                    mma_f16(d, arlo[mt].x, arhi[mt].x, arlo[mt].y, arhi[mt].y, bv.x, bv.y);
                    afrag[mt][2 * half]     = pack2(silu_tanh(d[0]), silu_tanh(d[1]));
                    afrag[mt][2 * half + 1] = pack2(silu_tanh(d[2]), silu_tanh(d[3]));
                }
            }
#pragma unroll
            for (int nt = 0; nt < 8; nt++) {
                uint2 bv = *(const uint2*)(smem + OFF_BT2 + ks * 4096 +
                                           (n0 + 8 * nt + q) * 32 + 8 * c);
                mma_f16(dacc[0][nt], afrag[0][0], afrag[0][1], afrag[0][2], afrag[0][3],
                        bv.x, bv.y);
                mma_f16(dacc[1][nt], afrag[1][0], afrag[1][1], afrag[1][2], afrag[1][3],
                        bv.x, bv.y);
            }
        }

        // ---- epilogue: out = silu(D + EW1[zi] + EW2[zj]) ----
#pragma unroll
        for (int mt = 0; mt < 2; mt++) {
#pragma unroll
            for (int sub = 0; sub < 2; sub++) {
                int r = m0 + 16 * mt + 8 * sub + q;
                long e = base + r;
                if (e < N_EDGES_) {
                    int zi = zi_s[r], zj = zj_s[r];
                    const float* p1 = g_EW1 + zi * EMB;
                    const float* p2 = g_EW2 + zj * EMB;
                    float* op = out + (size_t)e * EMB;
#pragma unroll
                    for (int nt = 0; nt < 8; nt++) {
                        int n = n0 + 8 * nt + 2 * c;
                        float2 w1 = *(const float2*)(p1 + n);
                        float2 w2 = *(const float2*)(p2 + n);
                        float2 o;
                        o.x = silu_tanh(dacc[mt][nt][2 * sub + 0] + w1.x + w2.x);
                        o.y = silu_tanh(dacc[mt][nt][2 * sub + 1] + w1.y + w2.y);
                        *(float2*)(op + n) = o;
                    }
                }
            }
        }

        // ---- store prefetched staging data into the other buffer ----
        {
            int nb = buf ^ 1;
            uint32_t* dst = (uint32_t*)(smem + OFF_RBFH + nb * 4096 + prow * 32 + ph * 4);
            dst[0] = pack2(pa.x, pa.y); dst[2] = pack2(pa.z, pa.w);
            dst[4] = pack2(pb.x, pb.y); dst[6] = pack2(pb.z, pb.w);
            ((int*)(smem + (zsel ? OFF_ZJ : OFF_ZI) + nb * 512))[zrow] = pz;
        }
        __syncthreads();
        buf ^= 1;
    }
}

// ---------------- launch ----------------
extern "C" void kernel_launch(void* const* d_in, const int* in_sizes, int n_in,
                              void* d_out, int out_size) {
    (void)in_sizes; (void)n_in; (void)out_size;
    const int*   Z     = (const int*)d_in[0];
    const float* rbf   = (const float*)d_in[1];
    const int*   idx_i = (const int*)d_in[2];
    const int*   idx_j = (const int*)d_in[3];
    const float* emb   = (const float*)d_in[4];
    const float* W_rbf = (const float*)d_in[5];
    const float* b_rbf = (const float*)d_in[6];
    const float* W     = (const float*)d_in[7];
    const float* b     = (const float*)d_in[8];
    float* out  = (float*)d_out;
    float* out0 = out + (size_t)N_EDGES_ * EMB;

    prep_kernel<<<N_ELEM, 256>>>(emb, W, b);
    main_kernel<<<GRID_MAIN, THREADS>>>(Z, rbf, idx_i, idx_j, W_rbf, b_rbf, W, out,
                                        emb, out0);
}

// round 10
// speedup vs baseline: 1.3818x; 1.3818x over previous
#include <cuda_runtime.h>
#include <cuda_fp16.h>
#include <cstdint>

#define EMB      128
#define NRAD     16
#define N_ATOMS_ 100000
#define N_EDGES_ 1000000
#define N_ELEM   95
#define TILE     128
#define NTILES   ((N_EDGES_ + TILE - 1) / TILE)   // 7813
#define GRID_MAIN 296
#define THREADS  256

// ---------------- smem layout (bytes) ----------------
// BT2: W3^T fp16, LDS.128 layout [ks(8)][ntp(4x2)][q(8)][c(4)] x16B = 32KB
// BT1: W_rbf^T fp16 [ntp(8)][q(8)][c(4)] x16B = 4KB
// RBFH: rbf tile fp16 [rblk(8)][q(8)][c(4)] x16B (rows q, q+8 paired), x2 = 8KB
#define OFF_BT2   0
#define OFF_BT1   32768
#define OFF_RBFH  36864
#define OFF_BIAS  45056
#define OFF_ZI    45568
#define OFF_ZJ    46592
#define SMEM_TOTAL 47616

// fp16 embedding-projection tables, fragment-swizzled (half index):
// n = 32Q + 8s + 2c + b  ->  pos = z*128 + Q*32 + c*8 + s*2 + b
__device__ __align__(16) __half g_EW1h[N_ELEM * EMB];
__device__ __align__(16) __half g_EW2h[N_ELEM * EMB];

// ---------------- helpers ----------------
__device__ __forceinline__ float silu_tanh(float x) {
    float t;
    asm("tanh.approx.f32 %0, %1;" : "=f"(t) : "f"(0.5f * x));
    return 0.5f * x * (1.0f + t);
}
__device__ __forceinline__ uint32_t pack2(float lo, float hi) {
    uint32_t r;
    asm("cvt.rn.f16x2.f32 %0, %1, %2;" : "=r"(r) : "f"(hi), "f"(lo));
    return r;
}
__device__ __forceinline__ void mma_f16(float* d,
    uint32_t a0, uint32_t a1, uint32_t a2, uint32_t a3,
    uint32_t b0, uint32_t b1) {
    asm volatile(
        "mma.sync.aligned.m16n8k16.row.col.f32.f16.f16.f32 "
        "{%0,%1,%2,%3}, {%4,%5,%6,%7}, {%8,%9}, {%0,%1,%2,%3};"
        : "+f"(d[0]), "+f"(d[1]), "+f"(d[2]), "+f"(d[3])
        : "r"(a0), "r"(a1), "r"(a2), "r"(a3), "r"(b0), "r"(b1));
}
// physical half position inside a 16-half fragment chunk
__device__ __forceinline__ int physmap(int kk) {
    return 4 * ((kk & 7) >> 1) + 2 * (kk >> 3) + (kk & 1);
}

// ---------------- precompute: EW1h = emb@W1 + b, EW2h = emb@W2 (swizzled fp16) ----------------
__global__ void prep_kernel(const float* __restrict__ emb, const float* __restrict__ W,
                            const float* __restrict__ b) {
    __shared__ float p1[EMB], p2[EMB];
    int z = blockIdx.x, n = threadIdx.x & 127, h = threadIdx.x >> 7;
    const float* er = emb + z * EMB;
    float s1 = 0.0f, s2 = 0.0f;
    int k0 = h * 64;
#pragma unroll 8
    for (int k = k0; k < k0 + 64; k++) {
        float ev = er[k];
        s1 += ev * W[k * EMB + n];
        s2 += ev * W[(EMB + k) * EMB + n];
    }
    if (h) { p1[n] = s1; p2[n] = s2; }
    __syncthreads();
    if (!h) {
        int Q = n >> 5, s = (n >> 3) & 3, c = (n >> 1) & 3, bb = n & 1;
        int pos = z * 128 + Q * 32 + c * 8 + s * 2 + bb;   // half index (FIXED)
        g_EW1h[pos] = __float2half(s1 + p1[n] + b[n]);
        g_EW2h[pos] = __float2half(s2 + p2[n]);
    }
}

// ---------------- main fused edge kernel (also does x_0 copy) ----------------
__global__ void __launch_bounds__(THREADS, 2)
main_kernel(const int* __restrict__ Z, const float* __restrict__ rbf,
            const int* __restrict__ idx_i, const int* __restrict__ idx_j,
            const float* __restrict__ W_rbf, const float* __restrict__ b_rbf,
            const float* __restrict__ W, float* __restrict__ out,
            const float* __restrict__ emb, float* __restrict__ out0) {
    __shared__ char smem[SMEM_TOTAL];
    const int tid  = threadIdx.x;
    const int wid  = tid >> 5, lane = tid & 31;
    const int q    = lane >> 2, c = lane & 3;
    const int m0   = (wid & 3) * 32;     // warp's 32 rows (2 m-tiles)
    const int n0   = (wid >> 2) * 64;    // warp's n-half
    const int ntpb = n0 >> 4;            // global ntp base (0 or 4)
    const int Qb   = n0 >> 5;            // global Q base (0 or 2)

    // staging maps
    const int prow = tid >> 1, ph = tid & 1;     // rbf: 2 threads/row
    const int srp  = prow >> 4, sq = prow & 7, shi = (prow >> 3) & 1;
    const int zrow = tid & 127, zsel = tid >> 7; // z: 128 zi + 128 zj

    // ---- x_0 = embeddings[Z] (independent; overlaps smem fills) ----
    for (int i = blockIdx.x * THREADS + tid; i < N_ATOMS_ * (EMB / 4);
         i += GRID_MAIN * THREADS) {
        int a = i >> 5, qq = i & 31;
        ((float4*)out0)[(size_t)a * 32 + qq] = ((const float4*)emb)[(size_t)Z[a] * 32 + qq];
    }

    // ---- one-time fills ----
    // BT1: W_rbf^T, nt1-paired LDS.128 layout
    for (int idx = tid; idx < EMB * NRAD; idx += THREADS) {
        int n = idx & 127, k = idx >> 7;
        int nt1 = n >> 3, qn = n & 7, p = physmap(k);
        int cc = p >> 2, slot = p & 3, side = nt1 & 1, ntp = nt1 >> 1;
        __half h = __float2half(W_rbf[k * EMB + n]);
        *(unsigned short*)(smem + OFF_BT1 + ntp * 512 + qn * 64 + cc * 16 +
                           side * 8 + slot * 2) = __half_as_ushort(h);
    }
    // BT2: W3^T, nt-paired LDS.128 layout
    for (int idx = tid; idx < EMB * EMB; idx += THREADS) {
        int n = idx & 127, k = idx >> 7;
        int ks = k >> 4, kk = k & 15, p = physmap(kk);
        int cc = p >> 2, slot = p & 3;
        int ntg = n >> 3, qn = n & 7, ntp = ntg >> 1, side = ntg & 1;
        __half h = __float2half(W[(2 * EMB + k) * EMB + n]);   // W3[k][n]
        *(unsigned short*)(smem + OFF_BT2 + ks * 4096 + ntp * 512 + qn * 64 + cc * 16 +
                           side * 8 + slot * 2) = __half_as_ushort(h);
    }
    if (tid < EMB) ((float*)(smem + OFF_BIAS))[tid] = b_rbf[tid];

    // ---- prologue: stage first tile into buffer 0 ----
    int t = blockIdx.x;
    {
        long eb = (long)t * TILE;
        long e  = eb + prow; if (e >= N_EDGES_) e = N_EDGES_ - 1;
        float4 a = ((const float4*)rbf)[e * 4 + ph];       // k 4ph..4ph+3
        float4 b = ((const float4*)rbf)[e * 4 + ph + 2];   // k 8+4ph..
        long ez = eb + zrow; if (ez >= N_EDGES_) ez = N_EDGES_ - 1;
        int pz = Z[(zsel ? idx_j : idx_i)[ez]];
        char* rbb = smem + OFF_RBFH + srp * 512 + sq * 64 + shi * 8;
        *(uint2*)(rbb + (2 * ph) * 16)     = make_uint2(pack2(a.x, a.y), pack2(b.x, b.y));
        *(uint2*)(rbb + (2 * ph + 1) * 16) = make_uint2(pack2(a.z, a.w), pack2(b.z, b.w));
        ((int*)(smem + (zsel ? OFF_ZJ : OFF_ZI)))[zrow] = pz;
    }
    __syncthreads();

    int buf = 0;
    for (; t < NTILES; t += GRID_MAIN) {
        // ---- prefetch next tile's staging data ----
        float4 pa, pb; int pz;
        {
            int tn = t + GRID_MAIN;
            long eb = (long)(tn < NTILES ? tn : t) * TILE;
            long e  = eb + prow; if (e >= N_EDGES_) e = N_EDGES_ - 1;
            pa = ((const float4*)rbf)[e * 4 + ph];
            pb = ((const float4*)rbf)[e * 4 + ph + 2];
            long ez = eb + zrow; if (ez >= N_EDGES_) ez = N_EDGES_ - 1;
            pz = Z[(zsel ? idx_j : idx_i)[ez]];
        }

        const long base = (long)t * TILE;
        const char* rb  = smem + OFF_RBFH + buf * 4096;
        const int* zi_s = (const int*)(smem + OFF_ZI + buf * 512);
        const int* zj_s = (const int*)(smem + OFF_ZJ + buf * 512);

        // ---- A operands for GEMM1: one LDS.128 per m-tile ----
        uint4 ar[2];
#pragma unroll
        for (int mt = 0; mt < 2; mt++)
            ar[mt] = *(const uint4*)(rb + (m0 / 16 + mt) * 512 + q * 64 + c * 16);

        // ---- fused GEMM1 -> silu -> GEMM2, one k-step at a time ----
        float dacc[2][8][4];
#pragma unroll
        for (int mt = 0; mt < 2; mt++)
#pragma unroll
            for (int nt = 0; nt < 8; nt++)
#pragma unroll
                for (int r = 0; r < 4; r++) dacc[mt][nt][r] = 0.0f;

        const float* bias_s = (const float*)(smem + OFF_BIAS);
#pragma unroll
        for (int ks = 0; ks < 8; ks++) {
            uint4 b1v = *(const uint4*)(smem + OFF_BT1 + ks * 512 + q * 64 + c * 16);
            float2 bb0 = *(const float2*)(bias_s + 16 * ks + 2 * c);
            float2 bb1 = *(const float2*)(bias_s + 16 * ks + 8 + 2 * c);
            uint32_t afrag[2][4];
#pragma unroll
            for (int mt = 0; mt < 2; mt++) {
                float d0[4] = {bb0.x, bb0.y, bb0.x, bb0.y};
                mma_f16(d0, ar[mt].x, ar[mt].z, ar[mt].y, ar[mt].w, b1v.x, b1v.y);
                afrag[mt][0] = pack2(silu_tanh(d0[0]), silu_tanh(d0[1]));
                afrag[mt][1] = pack2(silu_tanh(d0[2]), silu_tanh(d0[3]));
                float d1[4] = {bb1.x, bb1.y, bb1.x, bb1.y};
                mma_f16(d1, ar[mt].x, ar[mt].z, ar[mt].y, ar[mt].w, b1v.z, b1v.w);
                afrag[mt][2] = pack2(silu_tanh(d1[0]), silu_tanh(d1[1]));
                afrag[mt][3] = pack2(silu_tanh(d1[2]), silu_tanh(d1[3]));
            }
#pragma unroll
            for (int ntp = 0; ntp < 4; ntp++) {
                uint4 bv = *(const uint4*)(smem + OFF_BT2 + ks * 4096 +
                                           (ntpb + ntp) * 512 + q * 64 + c * 16);
                mma_f16(dacc[0][2 * ntp],     afrag[0][0], afrag[0][1], afrag[0][2],
                        afrag[0][3], bv.x, bv.y);
                mma_f16(dacc[1][2 * ntp],     afrag[1][0], afrag[1][1], afrag[1][2],
                        afrag[1][3], bv.x, bv.y);
                mma_f16(dacc[0][2 * ntp + 1], afrag[0][0], afrag[0][1], afrag[0][2],
                        afrag[0][3], bv.z, bv.w);
                mma_f16(dacc[1][2 * ntp + 1], afrag[1][0], afrag[1][1], afrag[1][2],
                        afrag[1][3], bv.z, bv.w);
            }
        }

        // ---- epilogue: out = silu(D + EW1[zi] + EW2[zj]), fp16 LDG.128 gathers ----
#pragma unroll
        for (int mt = 0; mt < 2; mt++) {
#pragma unroll
            for (int sub = 0; sub < 2; sub++) {
                int r = m0 + 16 * mt + 8 * sub + q;
                long e = base + r;
                if (e < N_EDGES_) {
                    int zi = zi_s[r], zj = zj_s[r];
                    const __half* h1 = g_EW1h + zi * EMB;
                    const __half* h2 = g_EW2h + zj * EMB;
                    float* op = out + (size_t)e * EMB;
#pragma unroll
                    for (int Q = 0; Q < 2; Q++) {
                        // half index: (Qb+Q)*32 + c*8  (FIXED)
                        uint4 u1 = *(const uint4*)(h1 + (Qb + Q) * 32 + c * 8);
                        uint4 u2 = *(const uint4*)(h2 + (Qb + Q) * 32 + c * 8);
                        __half2 s0 = __hadd2(*(const __half2*)&u1.x, *(const __half2*)&u2.x);
                        __half2 s1 = __hadd2(*(const __half2*)&u1.y, *(const __half2*)&u2.y);
                        __half2 s2 = __hadd2(*(const __half2*)&u1.z, *(const __half2*)&u2.z);
                        __half2 s3 = __hadd2(*(const __half2*)&u1.w, *(const __half2*)&u2.w);
                        float2 w0 = __half22float2(s0);
                        float2 w1 = __half22float2(s1);
                        float2 w2 = __half22float2(s2);
                        float2 w3 = __half22float2(s3);
                        int ntl = 4 * Q;
                        float2 o;
                        o.x = silu_tanh(dacc[mt][ntl][2 * sub + 0] + w0.x);
                        o.y = silu_tanh(dacc[mt][ntl][2 * sub + 1] + w0.y);
                        *(float2*)(op + n0 + 8 * ntl + 2 * c) = o;
                        o.x = silu_tanh(dacc[mt][ntl + 1][2 * sub + 0] + w1.x);
                        o.y = silu_tanh(dacc[mt][ntl + 1][2 * sub + 1] + w1.y);
                        *(float2*)(op + n0 + 8 * (ntl + 1) + 2 * c) = o;
                        o.x = silu_tanh(dacc[mt][ntl + 2][2 * sub + 0] + w2.x);
                        o.y = silu_tanh(dacc[mt][ntl + 2][2 * sub + 1] + w2.y);
                        *(float2*)(op + n0 + 8 * (ntl + 2) + 2 * c) = o;
                        o.x = silu_tanh(dacc[mt][ntl + 3][2 * sub + 0] + w3.x);
                        o.y = silu_tanh(dacc[mt][ntl + 3][2 * sub + 1] + w3.y);
                        *(float2*)(op + n0 + 8 * (ntl + 3) + 2 * c) = o;
                    }
                }
            }
        }

        // ---- store prefetched staging data into the other buffer ----
        {
            int nb = buf ^ 1;
            char* rbb = smem + OFF_RBFH + nb * 4096 + srp * 512 + sq * 64 + shi * 8;
            *(uint2*)(rbb + (2 * ph) * 16)     = make_uint2(pack2(pa.x, pa.y), pack2(pb.x, pb.y));
            *(uint2*)(rbb + (2 * ph + 1) * 16) = make_uint2(pack2(pa.z, pa.w), pack2(pb.z, pb.w));
            ((int*)(smem + (zsel ? OFF_ZJ : OFF_ZI) + nb * 512))[zrow] = pz;
        }
        __syncthreads();
        buf ^= 1;
    }
}

// ---------------- launch ----------------
extern "C" void kernel_launch(void* const* d_in, const int* in_sizes, int n_in,
                              void* d_out, int out_size) {
    (void)in_sizes; (void)n_in; (void)out_size;
    const int*   Z     = (const int*)d_in[0];
    const float* rbf   = (const float*)d_in[1];
    const int*   idx_i = (const int*)d_in[2];
    const int*   idx_j = (const int*)d_in[3];
    const float* emb   = (const float*)d_in[4];
    const float* W_rbf = (const float*)d_in[5];
    const float* b_rbf = (const float*)d_in[6];
    const float* W     = (const float*)d_in[7];
    const float* b     = (const float*)d_in[8];
    float* out  = (float*)d_out;
    float* out0 = out + (size_t)N_EDGES_ * EMB;

    prep_kernel<<<N_ELEM, 256>>>(emb, W, b);
    main_kernel<<<GRID_MAIN, THREADS>>>(Z, rbf, idx_i, idx_j, W_rbf, b_rbf, W, out,
                                        emb, out0);
}